// round 16
// baseline (speedup 1.0000x reference)
#include <cuda_runtime.h>
#include <cuda_bf16.h>
#include <cstdint>

#define NODES    100000
#define NODES_PAD 100096          // 782 * 128
#define C        256
#define GRAPHS   64
#define OUTC     10
#define EMAX     1600000
#define NB1024   ((NODES + 1023) / 1024)

// ---------------- scratch (static device globals; no allocation) ----------
__device__ __align__(16) __nv_bfloat16 g_A[(size_t)NODES_PAD * C];  // bf16(x*dinv)
__device__ __align__(16) __nv_bfloat16 g_B[(size_t)C * C];          // bf16(W1^T)
__device__ __align__(16) uint32_t g_hsb[(size_t)NODES_PAD * (C / 2)]; // bf16x2
__device__ float g_dinv[NODES];
__device__ int   g_degi[NODES];
__device__ int   g_rowptr[NODES + 1];
__device__ int   g_cursor[NODES];
__device__ int   g_elist[EMAX];
__device__ int   g_bsum[NB1024 + 1];
__device__ float g_sums[GRAPHS * C];
__device__ float g_counts[GRAPHS];
__device__ int   g_is64;

// ---------------- helpers ------------------------------------------------
__device__ __forceinline__ int load_idx(const void* p, long long i, int is64) {
    if (is64) return (int)((const long long*)p)[i];
    return ((const int*)p)[i];
}

__device__ __forceinline__ void mma16816(float* c, const uint32_t* a,
                                         const uint32_t* b) {
    asm volatile(
        "mma.sync.aligned.m16n8k16.row.col.f32.bf16.bf16.f32 "
        "{%0,%1,%2,%3}, {%4,%5,%6,%7}, {%8,%9}, {%0,%1,%2,%3};"
        : "+f"(c[0]), "+f"(c[1]), "+f"(c[2]), "+f"(c[3])
        : "r"(a[0]), "r"(a[1]), "r"(a[2]), "r"(a[3]), "r"(b[0]), "r"(b[1]));
}

__device__ __forceinline__ uint32_t smem_u32(const void* p) {
    uint32_t a;
    asm("{ .reg .u64 t; cvta.to.shared.u64 t, %1; cvt.u32.u64 %0, t; }"
        : "=r"(a) : "l"(p));
    return a;
}
__device__ __forceinline__ void cp16(uint32_t dst, const void* src) {
    asm volatile("cp.async.ca.shared.global [%0], [%1], 16;"
                 :: "r"(dst), "l"(src) : "memory");
}
#define CP_COMMIT() asm volatile("cp.async.commit_group;" ::: "memory")
#define CP_WAIT(N)  asm volatile("cp.async.wait_group %0;" :: "n"(N) : "memory")

// ---------------------------------------------------------------------------
// fused: index-dtype detect (1 thread) + zero degi/sums/counts
__global__ void init_kernel(const int* __restrict__ ei32, int n) {
    int i = blockIdx.x * blockDim.x + threadIdx.x;
    if (i == 0) {
        int nz = 0;
        #pragma unroll
        for (int k = 1; k < 256; k += 2) nz |= (ei32[k] != 0);
        g_is64 = (nz == 0) ? 1 : 0;
    }
    if (i < n) g_degi[i] = 0;
    if (i < GRAPHS * C) g_sums[i] = 0.f;
    if (i < GRAPHS) g_counts[i] = 0.f;
}

// degree histogram, 4 edges per thread (vectorized when aligned)
__global__ void degi_kernel(const void* __restrict__ ei, int E) {
    int e4 = (blockIdx.x * blockDim.x + threadIdx.x) * 4;
    if (e4 >= E) return;
    int is64 = g_is64;
    if (e4 + 4 <= E && (E & 3) == 0) {
        int d0, d1, d2, d3;
        if (is64) {
            const long long* p = (const long long*)ei + E + e4;
            longlong2 v0 = *(const longlong2*)p;
            longlong2 v1 = *(const longlong2*)(p + 2);
            d0 = (int)v0.x; d1 = (int)v0.y; d2 = (int)v1.x; d3 = (int)v1.y;
        } else {
            int4 v = *(const int4*)((const int*)ei + E + e4);
            d0 = v.x; d1 = v.y; d2 = v.z; d3 = v.w;
        }
        atomicAdd(&g_degi[d0], 1);
        atomicAdd(&g_degi[d1], 1);
        atomicAdd(&g_degi[d2], 1);
        atomicAdd(&g_degi[d3], 1);
    } else {
        for (int e = e4; e < min(e4 + 4, E); e++)
            atomicAdd(&g_degi[load_idx(ei, (long long)E + e, is64)], 1);
    }
}

// ---------------- hierarchical scan ----------------------------------------
__global__ void scan1_kernel(int n) {
    __shared__ int wsum[32];
    int t = threadIdx.x;
    int i = blockIdx.x * 1024 + t;
    int v = (i < n) ? g_degi[i] : 0;
    int lane = t & 31, w = t >> 5;
    int inc = v;
    #pragma unroll
    for (int d = 1; d < 32; d <<= 1) {
        int u = __shfl_up_sync(0xFFFFFFFFu, inc, d);
        if (lane >= d) inc += u;
    }
    if (lane == 31) wsum[w] = inc;
    __syncthreads();
    if (w == 0) {
        int x = wsum[lane];
        #pragma unroll
        for (int d = 1; d < 32; d <<= 1) {
            int u = __shfl_up_sync(0xFFFFFFFFu, x, d);
            if (lane >= d) x += u;
        }
        wsum[lane] = x;
    }
    __syncthreads();
    int excl = inc - v + (w ? wsum[w - 1] : 0);
    if (i < n) g_rowptr[i] = excl;
    if (t == 1023) g_bsum[blockIdx.x] = excl + v;
}

__global__ void scan2_kernel(int nb) {
    __shared__ int wsum[32];
    int t = threadIdx.x;                     // 1024 threads
    int v = (t < nb) ? g_bsum[t] : 0;
    int lane = t & 31, w = t >> 5;
    int inc = v;
    #pragma unroll
    for (int d = 1; d < 32; d <<= 1) {
        int u = __shfl_up_sync(0xFFFFFFFFu, inc, d);
        if (lane >= d) inc += u;
    }
    if (lane == 31) wsum[w] = inc;
    __syncthreads();
    if (w == 0) {
        int x = wsum[lane];
        #pragma unroll
        for (int d = 1; d < 32; d <<= 1) {
            int u = __shfl_up_sync(0xFFFFFFFFu, x, d);
            if (lane >= d) x += u;
        }
        wsum[lane] = x;
    }
    __syncthreads();
    int excl = inc - v + (w ? wsum[w - 1] : 0);
    if (t < nb) g_bsum[t] = excl;
}

// fixup + cursor + dinv + graph node counts (fused bcount)
__global__ void scan3_kernel(const void* __restrict__ batch, int n) {
    int i = blockIdx.x * blockDim.x + threadIdx.x;
    if (i >= n) return;
    int d = g_degi[i];
    int r = g_rowptr[i] + g_bsum[i >> 10];
    g_rowptr[i] = r;
    g_cursor[i] = r;
    g_dinv[i] = rsqrtf((float)d + 1.f);
    if (i == n - 1) g_rowptr[n] = r + d;
    atomicAdd(&g_counts[load_idx(batch, i, g_is64)], 1.f);
}

// edge placement, 4 edges per thread (vectorized when aligned)
__global__ void place_kernel(const void* __restrict__ ei, int E) {
    int e4 = (blockIdx.x * blockDim.x + threadIdx.x) * 4;
    if (e4 >= E) return;
    int is64 = g_is64;
    if (e4 + 4 <= E && (E & 3) == 0) {
        int s0, s1, s2, s3, d0, d1, d2, d3;
        if (is64) {
            const long long* ps = (const long long*)ei + e4;
            longlong2 a0 = *(const longlong2*)ps;
            longlong2 a1 = *(const longlong2*)(ps + 2);
            const long long* pd = (const long long*)ei + E + e4;
            longlong2 b0 = *(const longlong2*)pd;
            longlong2 b1 = *(const longlong2*)(pd + 2);
            s0 = (int)a0.x; s1 = (int)a0.y; s2 = (int)a1.x; s3 = (int)a1.y;
            d0 = (int)b0.x; d1 = (int)b0.y; d2 = (int)b1.x; d3 = (int)b1.y;
        } else {
            int4 a = *(const int4*)((const int*)ei + e4);
            int4 b = *(const int4*)((const int*)ei + E + e4);
            s0 = a.x; s1 = a.y; s2 = a.z; s3 = a.w;
            d0 = b.x; d1 = b.y; d2 = b.z; d3 = b.w;
        }
        g_elist[atomicAdd(&g_cursor[d0], 1)] = s0;
        g_elist[atomicAdd(&g_cursor[d1], 1)] = s1;
        g_elist[atomicAdd(&g_cursor[d2], 1)] = s2;
        g_elist[atomicAdd(&g_cursor[d3], 1)] = s3;
    } else {
        for (int e = e4; e < min(e4 + 4, E); e++) {
            int src = load_idx(ei, e, is64);
            int dst = load_idx(ei, (long long)E + e, is64);
            g_elist[atomicAdd(&g_cursor[dst], 1)] = src;
        }
    }
}

// ---------------------------------------------------------------------------
// fused: A = bf16(x * dinv[row]) (8 ch/thread)  +  B = bf16(W1^T)
#define CONV_BLOCKS ((NODES_PAD * 32 + 255) / 256)
#define BB_BLOCKS   (C * C / 256)
__global__ void convert_kernel(const float* __restrict__ x,
                               const float* __restrict__ W1, int n) {
    if (blockIdx.x >= CONV_BLOCKS) {
        int idx = (blockIdx.x - CONV_BLOCKS) * blockDim.x + threadIdx.x;
        if (idx >= C * C) return;
        int nn = idx >> 8, k = idx & 255;
        g_B[(size_t)nn * C + k] = __float2bfloat16(W1[(size_t)k * C + nn]);
        return;
    }
    long long idx = (long long)blockIdx.x * blockDim.x + threadIdx.x;
    if (idx >= (long long)NODES_PAD * 32) return;
    int row = (int)(idx >> 5);
    int p = (int)(idx & 31);            // 8-channel group
    uint4 outv;
    if (row < n) {
        float d = g_dinv[row];
        float4 v0 = *(const float4*)(x + (size_t)row * C + p * 8);
        float4 v1 = *(const float4*)(x + (size_t)row * C + p * 8 + 4);
        __nv_bfloat162 h0 = __float22bfloat162_rn(make_float2(v0.x * d, v0.y * d));
        __nv_bfloat162 h1 = __float22bfloat162_rn(make_float2(v0.z * d, v0.w * d));
        __nv_bfloat162 h2 = __float22bfloat162_rn(make_float2(v1.x * d, v1.y * d));
        __nv_bfloat162 h3 = __float22bfloat162_rn(make_float2(v1.z * d, v1.w * d));
        outv = make_uint4(*(uint32_t*)&h0, *(uint32_t*)&h1,
                          *(uint32_t*)&h2, *(uint32_t*)&h3);
    } else {
        outv = make_uint4(0, 0, 0, 0);
    }
    *(uint4*)(g_A + (size_t)row * C + p * 8) = outv;
}

// ---------------------------------------------------------------------------
// bf16 mma.sync GEMM, K=256, cp.async double buffered; CTA tile 128x128 so
// 2 CTAs/SM co-reside (73.7KB smem). Warp grid 2(M) x 4(N); warp tile 64x32.
#define APAD 72
#define STG_ELEMS ((128 + 128) * APAD)

__device__ __forceinline__ void load_stage(uint32_t sbase, int tid, int m0,
                                           int n0, int kc, int s) {
    uint32_t As = sbase + (uint32_t)(s * STG_ELEMS) * 2;
    uint32_t Bs = As + 128 * APAD * 2;
    const __nv_bfloat16* Ab = g_A + (size_t)m0 * C + kc * 64;
    #pragma unroll
    for (int i = 0; i < 4; i++) {
        int u = tid + i * 256;
        int r = u >> 3, o = u & 7;
        cp16(As + (uint32_t)(r * APAD + o * 8) * 2,
             Ab + (size_t)r * C + o * 8);
    }
    const __nv_bfloat16* Bb = g_B + (size_t)n0 * C + kc * 64;
    #pragma unroll
    for (int i = 0; i < 4; i++) {
        int u = tid + i * 256;
        int r = u >> 3, o = u & 7;
        cp16(Bs + (uint32_t)(r * APAD + o * 8) * 2,
             Bb + (size_t)r * C + o * 8);
    }
    CP_COMMIT();
}

__global__ void __launch_bounds__(256) gemm_mma_kernel() {
    extern __shared__ __nv_bfloat16 smem[];

    int tid = threadIdx.x;
    int wid = tid >> 5, lane = tid & 31;
    int g = lane >> 2, tir = lane & 3;
    int wm = wid & 1, wn = wid >> 1;          // warp grid 2 x 4
    int m0 = blockIdx.x * 128;
    int n0 = blockIdx.y * 128;

    uint32_t sbase = smem_u32(smem);
    const int NKC = C / 64;                   // 4 chunks

    float c[4][4][4];
    #pragma unroll
    for (int mt = 0; mt < 4; mt++)
        #pragma unroll
        for (int nt = 0; nt < 4; nt++)
            #pragma unroll
            for (int q = 0; q < 4; q++) c[mt][nt][q] = 0.f;

    load_stage(sbase, tid, m0, n0, 0, 0);

    for (int kc = 0; kc < NKC; kc++) {
        if (kc + 1 < NKC) {
            load_stage(sbase, tid, m0, n0, kc + 1, (kc + 1) & 1);
            CP_WAIT(1);
        } else {
            CP_WAIT(0);
        }
        __syncthreads();

        const __nv_bfloat16* As = smem + (kc & 1) * STG_ELEMS;
        const __nv_bfloat16* Bs = As + 128 * APAD;

        #pragma unroll
        for (int ks = 0; ks < 4; ks++) {
            int kof = ks * 16 + tir * 2;
            uint32_t a[4][4];
            #pragma unroll
            for (int mt = 0; mt < 4; mt++) {
                int base = (wm * 64 + mt * 16 + g) * APAD + kof;
                a[mt][0] = *(const uint32_t*)(As + base);
                a[mt][1] = *(const uint32_t*)(As + base + 8 * APAD);
                a[mt][2] = *(const uint32_t*)(As + base + 8);
                a[mt][3] = *(const uint32_t*)(As + base + 8 * APAD + 8);
            }
            uint32_t b[4][2];
            #pragma unroll
            for (int nt = 0; nt < 4; nt++) {
                int base = (wn * 32 + nt * 8 + g) * APAD + kof;
                b[nt][0] = *(const uint32_t*)(Bs + base);
                b[nt][1] = *(const uint32_t*)(Bs + base + 8);
            }
            #pragma unroll
            for (int mt = 0; mt < 4; mt++)
                #pragma unroll
                for (int nt = 0; nt < 4; nt++)
                    mma16816(c[mt][nt], a[mt], b[nt]);
        }
        __syncthreads();
    }

    // epilogue: pack fp32 pair -> bf16x2, single 4B store per fragment half
    #pragma unroll
    for (int mt = 0; mt < 4; mt++) {
        int row = m0 + wm * 64 + mt * 16 + g;
        #pragma unroll
        for (int nt = 0; nt < 4; nt++) {
            int col2 = n0 / 2 + wn * 16 + nt * 4 + tir;   // (col)/2, col even
            __nv_bfloat162 p0 = __float22bfloat162_rn(
                make_float2(c[mt][nt][0], c[mt][nt][1]));
            __nv_bfloat162 p1 = __float22bfloat162_rn(
                make_float2(c[mt][nt][2], c[mt][nt][3]));
            g_hsb[(size_t)row * (C / 2) + col2]       = *(uint32_t*)&p0;
            g_hsb[(size_t)(row + 8) * (C / 2) + col2] = *(uint32_t*)&p1;
        }
    }
}

// ---------------------------------------------------------------------------
// fused CSR gather + relu + sorted-run mean-pool, uint2-wide (R12 shape).
// Block = 128 threads in two halves: half h (64 threads) processes nodes
// start+h, start+h+2, ... Each thread owns one uint2 word = 4 channels, so
// 64 threads cover a full 512B row; a warp reads 256B (2 lines) per LDG.
// NPB=32: 3125 blocks for better latency hiding / tail balance.
#define NPB 32
__global__ void __launch_bounds__(128) gather_pool_kernel(
        const void* __restrict__ batch, const float* __restrict__ b1, int n) {
    int t = threadIdx.x;
    int h = t >> 6;                      // node-parity half
    int q = t & 63;                      // uint2 word index; channels 4q..4q+3
    int start = blockIdx.x * NPB;
    if (start >= n) return;
    int end = min(start + NPB, n);
    int is64 = g_is64;

    float b0 = b1[4 * q + 0], bq1 = b1[4 * q + 1];
    float b2v = b1[4 * q + 2], b3v = b1[4 * q + 3];

    int first = start + h;
    if (first >= end) return;
    int gp = load_idx(batch, first, is64);
    float acc0 = 0.f, acc1 = 0.f, acc2 = 0.f, acc3 = 0.f;

    for (int i = first; i < end; i += 2) {
        int gid = load_idx(batch, i, is64);
        if (gid != gp) {
            atomicAdd(&g_sums[gp * C + 4 * q + 0], acc0);
            atomicAdd(&g_sums[gp * C + 4 * q + 1], acc1);
            atomicAdd(&g_sums[gp * C + 4 * q + 2], acc2);
            atomicAdd(&g_sums[gp * C + 4 * q + 3], acc3);
            acc0 = acc1 = acc2 = acc3 = 0.f;
            gp = gid;
        }

        int r0 = g_rowptr[i], r1 = g_rowptr[i + 1];
        uint2 w = ((const uint2*)(g_hsb + (size_t)i * 128))[q];   // self-loop
        float2 fa = __bfloat1622float2(*(__nv_bfloat162*)&w.x);
        float2 fb = __bfloat1622float2(*(__nv_bfloat162*)&w.y);
        float s0 = fa.x, s1 = fa.y, s2 = fb.x, s3 = fb.y;
        float u0 = 0.f, u1 = 0.f, u2 = 0.f, u3 = 0.f;

        int j = r0;
        for (; j + 4 <= r1; j += 4) {
            int e0 = g_elist[j],     e1 = g_elist[j + 1];
            int e2 = g_elist[j + 2], e3 = g_elist[j + 3];
            uint2 w0 = ((const uint2*)(g_hsb + (size_t)e0 * 128))[q];
            uint2 w1 = ((const uint2*)(g_hsb + (size_t)e1 * 128))[q];
            uint2 w2 = ((const uint2*)(g_hsb + (size_t)e2 * 128))[q];
            uint2 w3 = ((const uint2*)(g_hsb + (size_t)e3 * 128))[q];
            float2 a0 = __bfloat1622float2(*(__nv_bfloat162*)&w0.x);
            float2 a1 = __bfloat1622float2(*(__nv_bfloat162*)&w0.y);
            float2 c0 = __bfloat1622float2(*(__nv_bfloat162*)&w1.x);
            float2 c1 = __bfloat1622float2(*(__nv_bfloat162*)&w1.y);
            float2 d0 = __bfloat1622float2(*(__nv_bfloat162*)&w2.x);
            float2 d1 = __bfloat1622float2(*(__nv_bfloat162*)&w2.y);
            float2 e0f = __bfloat1622float2(*(__nv_bfloat162*)&w3.x);
            float2 e1f = __bfloat1622float2(*(__nv_bfloat162*)&w3.y);
            s0 += a0.x + d0.x; s1 += a0.y + d0.y;
            s2 += a1.x + d1.x; s3 += a1.y + d1.y;
            u0 += c0.x + e0f.x; u1 += c0.y + e0f.y;
            u2 += c1.x + e1f.x; u3 += c1.y + e1f.y;
        }
        for (; j < r1; j++) {
            uint2 wj = ((const uint2*)(g_hsb + (size_t)g_elist[j] * 128))[q];
            float2 a0 = __bfloat1622float2(*(__nv_bfloat162*)&wj.x);
            float2 a1 = __bfloat1622float2(*(__nv_bfloat162*)&wj.y);
            s0 += a0.x; s1 += a0.y; s2 += a1.x; s3 += a1.y;
        }

        float di = g_dinv[i];
        acc0 += fmaxf(di * (s0 + u0) + b0, 0.f);
        acc1 += fmaxf(di * (s1 + u1) + bq1, 0.f);
        acc2 += fmaxf(di * (s2 + u2) + b2v, 0.f);
        acc3 += fmaxf(di * (s3 + u3) + b3v, 0.f);
    }
    atomicAdd(&g_sums[gp * C + 4 * q + 0], acc0);
    atomicAdd(&g_sums[gp * C + 4 * q + 1], acc1);
    atomicAdd(&g_sums[gp * C + 4 * q + 2], acc2);
    atomicAdd(&g_sums[gp * C + 4 * q + 3], acc3);
}

// ---------------------------------------------------------------------------
__global__ void final_kernel(const float* __restrict__ W2,
                             const float* __restrict__ b2,
                             float* __restrict__ out) {
    int t = threadIdx.x;
    if (t >= GRAPHS * OUTC) return;
    int g = t / OUTC, o = t % OUTC;
    float s = 0.f;
    #pragma unroll 8
    for (int k = 0; k < C; k++)
        s += g_sums[g * C + k] * W2[k * OUTC + o];
    out[t] = s / fmaxf(g_counts[g], 1.f) + b2[o];
}

// ---------------------------------------------------------------------------
extern "C" void kernel_launch(void* const* d_in, const int* in_sizes, int n_in,
                              void* d_out, int out_size) {
    const float* x     = (const float*)d_in[0];
    const void*  ei    = d_in[1];
    const void*  batch = d_in[2];
    const float* W1    = (const float*)d_in[3];
    const float* b1    = (const float*)d_in[4];
    const float* W2    = (const float*)d_in[5];
    const float* b2    = (const float*)d_in[6];
    float* out = (float*)d_out;

    int n = in_sizes[0] / C;    // 100000
    int E = in_sizes[1] / 2;    // 1600000
    int nb = (n + 1023) / 1024;

    init_kernel<<<(n + 255) / 256, 256>>>((const int*)ei, n);
    degi_kernel<<<(E / 4 + 255) / 256, 256>>>(ei, E);
    scan1_kernel<<<nb, 1024>>>(n);
    scan2_kernel<<<1, 1024>>>(nb);
    scan3_kernel<<<(n + 255) / 256, 256>>>(batch, n);

    convert_kernel<<<CONV_BLOCKS + BB_BLOCKS, 256>>>(x, W1, n);

    static const int SMEM_BYTES = 2 * STG_ELEMS * 2;   // 73728
    cudaFuncSetAttribute(gemm_mma_kernel,
                         cudaFuncAttributeMaxDynamicSharedMemorySize, SMEM_BYTES);
    dim3 ggrid(NODES_PAD / 128, 2);
    gemm_mma_kernel<<<ggrid, 256, SMEM_BYTES>>>();

    place_kernel<<<(E / 4 + 255) / 256, 256>>>(ei, E);
    gather_pool_kernel<<<(n + NPB - 1) / NPB, 128>>>(batch, b1, n);
    final_kernel<<<1, 640>>>(W2, b2, out);
}

// round 17
// speedup vs baseline: 1.0032x; 1.0032x over previous
#include <cuda_runtime.h>
#include <cuda_bf16.h>
#include <cstdint>

#define NODES    100000
#define NODES_PAD 100096          // 782 * 128
#define C        256
#define GRAPHS   64
#define OUTC     10
#define EMAX     1600000
#define NB1024   ((NODES + 1023) / 1024)

// ---------------- scratch (static device globals; no allocation) ----------
__device__ __align__(16) __nv_bfloat16 g_A[(size_t)NODES_PAD * C];  // bf16(x*dinv)
__device__ __align__(16) __nv_bfloat16 g_B[(size_t)C * C];          // bf16(W1^T)
__device__ __align__(16) uint32_t g_hsb[(size_t)NODES_PAD * (C / 2)]; // bf16x2
__device__ float g_dinv[NODES];
__device__ int   g_degi[NODES];
__device__ int   g_rowptr[NODES + 1];
__device__ int   g_cursor[NODES];
__device__ int   g_elist[EMAX];
__device__ int   g_bsum[NB1024 + 1];
__device__ float g_sums[GRAPHS * C];
__device__ float g_counts[GRAPHS];
__device__ int   g_is64;

// ---------------- helpers ------------------------------------------------
__device__ __forceinline__ int load_idx(const void* p, long long i, int is64) {
    if (is64) return (int)((const long long*)p)[i];
    return ((const int*)p)[i];
}

__device__ __forceinline__ void mma16816(float* c, const uint32_t* a,
                                         const uint32_t* b) {
    asm volatile(
        "mma.sync.aligned.m16n8k16.row.col.f32.bf16.bf16.f32 "
        "{%0,%1,%2,%3}, {%4,%5,%6,%7}, {%8,%9}, {%0,%1,%2,%3};"
        : "+f"(c[0]), "+f"(c[1]), "+f"(c[2]), "+f"(c[3])
        : "r"(a[0]), "r"(a[1]), "r"(a[2]), "r"(a[3]), "r"(b[0]), "r"(b[1]));
}

__device__ __forceinline__ uint32_t smem_u32(const void* p) {
    uint32_t a;
    asm("{ .reg .u64 t; cvta.to.shared.u64 t, %1; cvt.u32.u64 %0, t; }"
        : "=r"(a) : "l"(p));
    return a;
}
__device__ __forceinline__ void cp16(uint32_t dst, const void* src) {
    asm volatile("cp.async.ca.shared.global [%0], [%1], 16;"
                 :: "r"(dst), "l"(src) : "memory");
}
#define CP_COMMIT() asm volatile("cp.async.commit_group;" ::: "memory")
#define CP_WAIT(N)  asm volatile("cp.async.wait_group %0;" :: "n"(N) : "memory")

// ---------------------------------------------------------------------------
// fused: index-dtype detect (1 thread) + zero degi/sums/counts
__global__ void init_kernel(const int* __restrict__ ei32, int n) {
    int i = blockIdx.x * blockDim.x + threadIdx.x;
    if (i == 0) {
        int nz = 0;
        #pragma unroll
        for (int k = 1; k < 256; k += 2) nz |= (ei32[k] != 0);
        g_is64 = (nz == 0) ? 1 : 0;
    }
    if (i < n) g_degi[i] = 0;
    if (i < GRAPHS * C) g_sums[i] = 0.f;
    if (i < GRAPHS) g_counts[i] = 0.f;
}

// degree histogram: ONE edge per thread (max atomic concurrency — R16's
// 4-edges/thread variant serialized dependent ATOMGs and regressed 58us)
__global__ void degi_kernel(const void* __restrict__ ei, int E) {
    int i = blockIdx.x * blockDim.x + threadIdx.x;
    if (i >= E) return;
    int d = load_idx(ei, (long long)E + i, g_is64);
    atomicAdd(&g_degi[d], 1);
}

// ---------------- hierarchical scan ----------------------------------------
__global__ void scan1_kernel(int n) {
    __shared__ int wsum[32];
    int t = threadIdx.x;
    int i = blockIdx.x * 1024 + t;
    int v = (i < n) ? g_degi[i] : 0;
    int lane = t & 31, w = t >> 5;
    int inc = v;
    #pragma unroll
    for (int d = 1; d < 32; d <<= 1) {
        int u = __shfl_up_sync(0xFFFFFFFFu, inc, d);
        if (lane >= d) inc += u;
    }
    if (lane == 31) wsum[w] = inc;
    __syncthreads();
    if (w == 0) {
        int x = wsum[lane];
        #pragma unroll
        for (int d = 1; d < 32; d <<= 1) {
            int u = __shfl_up_sync(0xFFFFFFFFu, x, d);
            if (lane >= d) x += u;
        }
        wsum[lane] = x;
    }
    __syncthreads();
    int excl = inc - v + (w ? wsum[w - 1] : 0);
    if (i < n) g_rowptr[i] = excl;
    if (t == 1023) g_bsum[blockIdx.x] = excl + v;
}

__global__ void scan2_kernel(int nb) {
    __shared__ int wsum[32];
    int t = threadIdx.x;                     // 1024 threads
    int v = (t < nb) ? g_bsum[t] : 0;
    int lane = t & 31, w = t >> 5;
    int inc = v;
    #pragma unroll
    for (int d = 1; d < 32; d <<= 1) {
        int u = __shfl_up_sync(0xFFFFFFFFu, inc, d);
        if (lane >= d) inc += u;
    }
    if (lane == 31) wsum[w] = inc;
    __syncthreads();
    if (w == 0) {
        int x = wsum[lane];
        #pragma unroll
        for (int d = 1; d < 32; d <<= 1) {
            int u = __shfl_up_sync(0xFFFFFFFFu, x, d);
            if (lane >= d) x += u;
        }
        wsum[lane] = x;
    }
    __syncthreads();
    int excl = inc - v + (w ? wsum[w - 1] : 0);
    if (t < nb) g_bsum[t] = excl;
}

// fixup + cursor + dinv + graph node counts (fused bcount)
__global__ void scan3_kernel(const void* __restrict__ batch, int n) {
    int i = blockIdx.x * blockDim.x + threadIdx.x;
    if (i >= n) return;
    int d = g_degi[i];
    int r = g_rowptr[i] + g_bsum[i >> 10];
    g_rowptr[i] = r;
    g_cursor[i] = r;
    g_dinv[i] = rsqrtf((float)d + 1.f);
    if (i == n - 1) g_rowptr[n] = r + d;
    atomicAdd(&g_counts[load_idx(batch, i, g_is64)], 1.f);
}

// edge placement: ONE edge per thread (see degi_kernel comment)
__global__ void place_kernel(const void* __restrict__ ei, int E) {
    int e = blockIdx.x * blockDim.x + threadIdx.x;
    if (e >= E) return;
    int is64 = g_is64;
    int src = load_idx(ei, e, is64);
    int dst = load_idx(ei, (long long)E + e, is64);
    int pos = atomicAdd(&g_cursor[dst], 1);
    g_elist[pos] = src;
}

// ---------------------------------------------------------------------------
// fused: A = bf16(x * dinv[row]) (8 ch/thread)  +  B = bf16(W1^T)
#define CONV_BLOCKS ((NODES_PAD * 32 + 255) / 256)
#define BB_BLOCKS   (C * C / 256)
__global__ void convert_kernel(const float* __restrict__ x,
                               const float* __restrict__ W1, int n) {
    if (blockIdx.x >= CONV_BLOCKS) {
        int idx = (blockIdx.x - CONV_BLOCKS) * blockDim.x + threadIdx.x;
        if (idx >= C * C) return;
        int nn = idx >> 8, k = idx & 255;
        g_B[(size_t)nn * C + k] = __float2bfloat16(W1[(size_t)k * C + nn]);
        return;
    }
    long long idx = (long long)blockIdx.x * blockDim.x + threadIdx.x;
    if (idx >= (long long)NODES_PAD * 32) return;
    int row = (int)(idx >> 5);
    int p = (int)(idx & 31);            // 8-channel group
    uint4 outv;
    if (row < n) {
        float d = g_dinv[row];
        float4 v0 = *(const float4*)(x + (size_t)row * C + p * 8);
        float4 v1 = *(const float4*)(x + (size_t)row * C + p * 8 + 4);
        __nv_bfloat162 h0 = __float22bfloat162_rn(make_float2(v0.x * d, v0.y * d));
        __nv_bfloat162 h1 = __float22bfloat162_rn(make_float2(v0.z * d, v0.w * d));
        __nv_bfloat162 h2 = __float22bfloat162_rn(make_float2(v1.x * d, v1.y * d));
        __nv_bfloat162 h3 = __float22bfloat162_rn(make_float2(v1.z * d, v1.w * d));
        outv = make_uint4(*(uint32_t*)&h0, *(uint32_t*)&h1,
                          *(uint32_t*)&h2, *(uint32_t*)&h3);
    } else {
        outv = make_uint4(0, 0, 0, 0);
    }
    *(uint4*)(g_A + (size_t)row * C + p * 8) = outv;
}

// ---------------------------------------------------------------------------
// bf16 mma.sync GEMM, K=256, cp.async double buffered; CTA tile 128x128 so
// 2 CTAs/SM co-reside (73.7KB smem). Warp grid 2(M) x 4(N); warp tile 64x32.
#define APAD 72
#define STG_ELEMS ((128 + 128) * APAD)

__device__ __forceinline__ void load_stage(uint32_t sbase, int tid, int m0,
                                           int n0, int kc, int s) {
    uint32_t As = sbase + (uint32_t)(s * STG_ELEMS) * 2;
    uint32_t Bs = As + 128 * APAD * 2;
    const __nv_bfloat16* Ab = g_A + (size_t)m0 * C + kc * 64;
    #pragma unroll
    for (int i = 0; i < 4; i++) {
        int u = tid + i * 256;
        int r = u >> 3, o = u & 7;
        cp16(As + (uint32_t)(r * APAD + o * 8) * 2,
             Ab + (size_t)r * C + o * 8);
    }
    const __nv_bfloat16* Bb = g_B + (size_t)n0 * C + kc * 64;
    #pragma unroll
    for (int i = 0; i < 4; i++) {
        int u = tid + i * 256;
        int r = u >> 3, o = u & 7;
        cp16(Bs + (uint32_t)(r * APAD + o * 8) * 2,
             Bb + (size_t)r * C + o * 8);
    }
    CP_COMMIT();
}

__global__ void __launch_bounds__(256) gemm_mma_kernel() {
    extern __shared__ __nv_bfloat16 smem[];

    int tid = threadIdx.x;
    int wid = tid >> 5, lane = tid & 31;
    int g = lane >> 2, tir = lane & 3;
    int wm = wid & 1, wn = wid >> 1;          // warp grid 2 x 4
    int m0 = blockIdx.x * 128;
    int n0 = blockIdx.y * 128;

    uint32_t sbase = smem_u32(smem);
    const int NKC = C / 64;                   // 4 chunks

    float c[4][4][4];
    #pragma unroll
    for (int mt = 0; mt < 4; mt++)
        #pragma unroll
        for (int nt = 0; nt < 4; nt++)
            #pragma unroll
            for (int q = 0; q < 4; q++) c[mt][nt][q] = 0.f;

    load_stage(sbase, tid, m0, n0, 0, 0);

    for (int kc = 0; kc < NKC; kc++) {
        if (kc + 1 < NKC) {
            load_stage(sbase, tid, m0, n0, kc + 1, (kc + 1) & 1);
            CP_WAIT(1);
        } else {
            CP_WAIT(0);
        }
        __syncthreads();

        const __nv_bfloat16* As = smem + (kc & 1) * STG_ELEMS;
        const __nv_bfloat16* Bs = As + 128 * APAD;

        #pragma unroll
        for (int ks = 0; ks < 4; ks++) {
            int kof = ks * 16 + tir * 2;
            uint32_t a[4][4];
            #pragma unroll
            for (int mt = 0; mt < 4; mt++) {
                int base = (wm * 64 + mt * 16 + g) * APAD + kof;
                a[mt][0] = *(const uint32_t*)(As + base);
                a[mt][1] = *(const uint32_t*)(As + base + 8 * APAD);
                a[mt][2] = *(const uint32_t*)(As + base + 8);
                a[mt][3] = *(const uint32_t*)(As + base + 8 * APAD + 8);
            }
            uint32_t b[4][2];
            #pragma unroll
            for (int nt = 0; nt < 4; nt++) {
                int base = (wn * 32 + nt * 8 + g) * APAD + kof;
                b[nt][0] = *(const uint32_t*)(Bs + base);
                b[nt][1] = *(const uint32_t*)(Bs + base + 8);
            }
            #pragma unroll
            for (int mt = 0; mt < 4; mt++)
                #pragma unroll
                for (int nt = 0; nt < 4; nt++)
                    mma16816(c[mt][nt], a[mt], b[nt]);
        }
        __syncthreads();
    }

    // epilogue: pack fp32 pair -> bf16x2, single 4B store per fragment half
    #pragma unroll
    for (int mt = 0; mt < 4; mt++) {
        int row = m0 + wm * 64 + mt * 16 + g;
        #pragma unroll
        for (int nt = 0; nt < 4; nt++) {
            int col2 = n0 / 2 + wn * 16 + nt * 4 + tir;   // (col)/2, col even
            __nv_bfloat162 p0 = __float22bfloat162_rn(
                make_float2(c[mt][nt][0], c[mt][nt][1]));
            __nv_bfloat162 p1 = __float22bfloat162_rn(
                make_float2(c[mt][nt][2], c[mt][nt][3]));
            g_hsb[(size_t)row * (C / 2) + col2]       = *(uint32_t*)&p0;
            g_hsb[(size_t)(row + 8) * (C / 2) + col2] = *(uint32_t*)&p1;
        }
    }
}

// ---------------------------------------------------------------------------
// fused CSR gather + relu + sorted-run mean-pool, uint2-wide (R12 shape).
// Block = 128 threads in two halves: half h (64 threads) processes nodes
// start+h, start+h+2, ... Each thread owns one uint2 word = 4 channels, so
// 64 threads cover a full 512B row; a warp reads 256B (2 lines) per LDG.
// NPB=32: 3125 blocks for better latency hiding / tail balance.
#define NPB 32
__global__ void __launch_bounds__(128) gather_pool_kernel(
        const void* __restrict__ batch, const float* __restrict__ b1, int n) {
    int t = threadIdx.x;
    int h = t >> 6;                      // node-parity half
    int q = t & 63;                      // uint2 word index; channels 4q..4q+3
    int start = blockIdx.x * NPB;
    if (start >= n) return;
    int end = min(start + NPB, n);
    int is64 = g_is64;

    float b0 = b1[4 * q + 0], bq1 = b1[4 * q + 1];
    float b2v = b1[4 * q + 2], b3v = b1[4 * q + 3];

    int first = start + h;
    if (first >= end) return;
    int gp = load_idx(batch, first, is64);
    float acc0 = 0.f, acc1 = 0.f, acc2 = 0.f, acc3 = 0.f;

    for (int i = first; i < end; i += 2) {
        int gid = load_idx(batch, i, is64);
        if (gid != gp) {
            atomicAdd(&g_sums[gp * C + 4 * q + 0], acc0);
            atomicAdd(&g_sums[gp * C + 4 * q + 1], acc1);
            atomicAdd(&g_sums[gp * C + 4 * q + 2], acc2);
            atomicAdd(&g_sums[gp * C + 4 * q + 3], acc3);
            acc0 = acc1 = acc2 = acc3 = 0.f;
            gp = gid;
        }

        int r0 = g_rowptr[i], r1 = g_rowptr[i + 1];
        uint2 w = ((const uint2*)(g_hsb + (size_t)i * 128))[q];   // self-loop
        float2 fa = __bfloat1622float2(*(__nv_bfloat162*)&w.x);
        float2 fb = __bfloat1622float2(*(__nv_bfloat162*)&w.y);
        float s0 = fa.x, s1 = fa.y, s2 = fb.x, s3 = fb.y;
        float u0 = 0.f, u1 = 0.f, u2 = 0.f, u3 = 0.f;

        int j = r0;
        for (; j + 4 <= r1; j += 4) {
            int e0 = g_elist[j],     e1 = g_elist[j + 1];
            int e2 = g_elist[j + 2], e3 = g_elist[j + 3];
            uint2 w0 = ((const uint2*)(g_hsb + (size_t)e0 * 128))[q];
            uint2 w1 = ((const uint2*)(g_hsb + (size_t)e1 * 128))[q];
            uint2 w2 = ((const uint2*)(g_hsb + (size_t)e2 * 128))[q];
            uint2 w3 = ((const uint2*)(g_hsb + (size_t)e3 * 128))[q];
            float2 a0 = __bfloat1622float2(*(__nv_bfloat162*)&w0.x);
            float2 a1 = __bfloat1622float2(*(__nv_bfloat162*)&w0.y);
            float2 c0 = __bfloat1622float2(*(__nv_bfloat162*)&w1.x);
            float2 c1 = __bfloat1622float2(*(__nv_bfloat162*)&w1.y);
            float2 d0 = __bfloat1622float2(*(__nv_bfloat162*)&w2.x);
            float2 d1 = __bfloat1622float2(*(__nv_bfloat162*)&w2.y);
            float2 e0f = __bfloat1622float2(*(__nv_bfloat162*)&w3.x);
            float2 e1f = __bfloat1622float2(*(__nv_bfloat162*)&w3.y);
            s0 += a0.x + d0.x; s1 += a0.y + d0.y;
            s2 += a1.x + d1.x; s3 += a1.y + d1.y;
            u0 += c0.x + e0f.x; u1 += c0.y + e0f.y;
            u2 += c1.x + e1f.x; u3 += c1.y + e1f.y;
        }
        for (; j < r1; j++) {
            uint2 wj = ((const uint2*)(g_hsb + (size_t)g_elist[j] * 128))[q];
            float2 a0 = __bfloat1622float2(*(__nv_bfloat162*)&wj.x);
            float2 a1 = __bfloat1622float2(*(__nv_bfloat162*)&wj.y);
            s0 += a0.x; s1 += a0.y; s2 += a1.x; s3 += a1.y;
        }

        float di = g_dinv[i];
        acc0 += fmaxf(di * (s0 + u0) + b0, 0.f);
        acc1 += fmaxf(di * (s1 + u1) + bq1, 0.f);
        acc2 += fmaxf(di * (s2 + u2) + b2v, 0.f);
        acc3 += fmaxf(di * (s3 + u3) + b3v, 0.f);
    }
    atomicAdd(&g_sums[gp * C + 4 * q + 0], acc0);
    atomicAdd(&g_sums[gp * C + 4 * q + 1], acc1);
    atomicAdd(&g_sums[gp * C + 4 * q + 2], acc2);
    atomicAdd(&g_sums[gp * C + 4 * q + 3], acc3);
}

// ---------------------------------------------------------------------------
__global__ void final_kernel(const float* __restrict__ W2,
                             const float* __restrict__ b2,
                             float* __restrict__ out) {
    int t = threadIdx.x;
    if (t >= GRAPHS * OUTC) return;
    int g = t / OUTC, o = t % OUTC;
    float s = 0.f;
    #pragma unroll 8
    for (int k = 0; k < C; k++)
        s += g_sums[g * C + k] * W2[k * OUTC + o];
    out[t] = s / fmaxf(g_counts[g], 1.f) + b2[o];
}

// ---------------------------------------------------------------------------
extern "C" void kernel_launch(void* const* d_in, const int* in_sizes, int n_in,
                              void* d_out, int out_size) {
    const float* x     = (const float*)d_in[0];
    const void*  ei    = d_in[1];
    const void*  batch = d_in[2];
    const float* W1    = (const float*)d_in[3];
    const float* b1    = (const float*)d_in[4];
    const float* W2    = (const float*)d_in[5];
    const float* b2    = (const float*)d_in[6];
    float* out = (float*)d_out;

    int n = in_sizes[0] / C;    // 100000
    int E = in_sizes[1] / 2;    // 1600000
    int nb = (n + 1023) / 1024;

    init_kernel<<<(n + 255) / 256, 256>>>((const int*)ei, n);
    degi_kernel<<<(E + 255) / 256, 256>>>(ei, E);
    scan1_kernel<<<nb, 1024>>>(n);
    scan2_kernel<<<1, 1024>>>(nb);
    scan3_kernel<<<(n + 255) / 256, 256>>>(batch, n);

    convert_kernel<<<CONV_BLOCKS + BB_BLOCKS, 256>>>(x, W1, n);

    static const int SMEM_BYTES = 2 * STG_ELEMS * 2;   // 73728
    cudaFuncSetAttribute(gemm_mma_kernel,
                         cudaFuncAttributeMaxDynamicSharedMemorySize, SMEM_BYTES);
    dim3 ggrid(NODES_PAD / 128, 2);
    gemm_mma_kernel<<<ggrid, 256, SMEM_BYTES>>>();

    place_kernel<<<(E + 255) / 256, 256>>>(ei, E);
    gather_pool_kernel<<<(n + NPB - 1) / NPB, 128>>>(batch, b1, n);
    final_kernel<<<1, 640>>>(W2, b2, out);
}